// round 17
// baseline (speedup 1.0000x reference)
#include <cuda_runtime.h>
#include <cuda_bf16.h>
#include <math.h>

#define B_   128
#define T_   512
#define NI   64
#define NH   1024
#define NO   64

#define NCTA  132            // 2 b-halves x (64 rec + 2 dec); 1 CTA/SM
#define NTHR  256
#define BNH   (B_ * NH)
#define PSTR  36             // padded floats per P row
#define SM_B0 0
#define SMEM_BYTES 131072    // B build 128KB; P (74KB) reuses it during steps

// ---------------- scratch ------------------------------------------------------
__device__ float g_enc[(size_t)T_ * B_ * NH];      // [t][b][h] fp32
// hidden in MMA-fragment-major layout:
// [buf][split][((kk*8 + mtile)*32 + lane)*4 + reg] (uint = 2 bf16)
__device__ unsigned g_hA[3][2][65536];
__device__ unsigned g_doneArr[2][64 * 8];          // per-producer flags, 32B stride
__device__ unsigned g_decc[2];

// ---------------- helpers ------------------------------------------------------
__device__ __forceinline__ unsigned smem_u32(const void* p) {
    unsigned a;
    asm("{ .reg .u64 t; cvta.to.shared.u64 t, %1; cvt.u32.u64 %0, t; }" : "=r"(a) : "l"(p));
    return a;
}
__device__ __forceinline__ void ldsm_x4t(unsigned r[4], unsigned addr) {
    asm volatile("ldmatrix.sync.aligned.m8n8.x4.trans.shared.b16 {%0,%1,%2,%3}, [%4];"
                 : "=r"(r[0]), "=r"(r[1]), "=r"(r[2]), "=r"(r[3]) : "r"(addr));
}
__device__ __forceinline__ void mma16816(float d[4], const unsigned a[4],
                                         unsigned b0, unsigned b1) {
    asm volatile(
        "mma.sync.aligned.m16n8k16.row.col.f32.bf16.bf16.f32 "
        "{%0,%1,%2,%3}, {%4,%5,%6,%7}, {%8,%9}, {%0,%1,%2,%3};"
        : "+f"(d[0]), "+f"(d[1]), "+f"(d[2]), "+f"(d[3])
        : "r"(a[0]), "r"(a[1]), "r"(a[2]), "r"(a[3]), "r"(b0), "r"(b1));
}
__device__ __forceinline__ void split_bf(float v, __nv_bfloat16& hi, __nv_bfloat16& lo) {
    hi = __float2bfloat16(v);
    lo = __float2bfloat16(v - __bfloat162float(hi));
}
__device__ __forceinline__ unsigned pack2(float a, float b) {
    __nv_bfloat162 t = __floats2bfloat162_rn(a, b);
    return *(unsigned*)&t;
}

// ---------------- reset + init --------------------------------------------------
__global__ void reset_kernel() {
    int i = threadIdx.x;
    for (int j = i; j < 2 * 64 * 8; j += 256) ((unsigned*)g_doneArr)[j] = 0;
    if (i < 2) g_decc[i] = 0;
}

__global__ void init_hidden_kernel(const float* __restrict__ hinit_w,
                                   const float* __restrict__ hinit_b) {
    int idx = blockIdx.x * blockDim.x + threadIdx.x;
    if (idx < B_ * NH) {
        int b = idx >> 10, h = idx & 1023;
        float v = hinit_w[h] + hinit_b[h];
        __nv_bfloat16 hi, lo;
        split_bf(v, hi, lo);
        int kk = h >> 4, mtile = b >> 4;
        int lanei = (b & 7) * 4 + ((h >> 1) & 3);
        int regi = ((b >> 3) & 1) + 2 * ((h >> 3) & 1);
        size_t e = ((size_t)((kk * 8 + mtile) * 32 + lanei) * 4 + regi) * 2 + (h & 1);
        ((__nv_bfloat16*)g_hA[0][0])[e] = hi;
        ((__nv_bfloat16*)g_hA[0][1])[e] = lo;
    }
}

// ---------------- encoder GEMM (one-shot), fp32 [t][b][h] ------------------------
__global__ void __launch_bounds__(256) enc_kernel(const float* __restrict__ x,
                                                  const float* __restrict__ enc_w,
                                                  const float* __restrict__ enc_b) {
    __shared__ float xs[32][NI + 1];
    __shared__ float ws[64][NI + 1];
    const int tid = threadIdx.x;
    const int tb0 = blockIdx.x * 32;
    const int h0  = blockIdx.y * 64;

    for (int i = tid; i < 32 * NI; i += 256) {
        int r = i >> 6, c = i & 63;
        int tb = tb0 + r;
        int t = tb >> 7, b = tb & 127;
        xs[r][c] = x[(size_t)b * (T_ * NI) + t * NI + c];
    }
    for (int i = tid; i < 64 * NI; i += 256) {
        int r = i >> 6, c = i & 63;
        ws[r][c] = enc_w[(h0 + r) * NI + c];
    }
    __syncthreads();

    const int rg = tid & 7;
    const int hg = tid >> 3;
    float acc[4][2] = {};
#pragma unroll
    for (int k = 0; k < NI; k++) {
        float w0 = ws[hg * 2 + 0][k];
        float w1 = ws[hg * 2 + 1][k];
#pragma unroll
        for (int j = 0; j < 4; j++) {
            float xv = xs[rg * 4 + j][k];
            acc[j][0] += xv * w0;
            acc[j][1] += xv * w1;
        }
    }
#pragma unroll
    for (int j = 0; j < 4; j++) {
        int tb = tb0 + rg * 4 + j;
#pragma unroll
        for (int q = 0; q < 2; q++) {
            int h = h0 + hg * 2 + q;
            g_enc[(size_t)tb * NH + h] = acc[j][q] + enc_b[h];
        }
    }
}

// ---------------- persistent mma.sync recurrent kernel ---------------------------
// CTA: jc = bid>>1 (0..65), bh = bid&1.
//   jc<64: rec tile, h cols jc*16..+15 (B cols interleaved R,F); jc>=64: dec tile.
// Warps: ko = wid (k-octant of 128). Per warp: n32, 4 m16 tiles, 8 k16 tiles.
// B fragments (hi+lo, 128 regs) resident across all steps.
// A fragments loaded DIRECTLY from fragment-major gmem (1 LDG.128 each).
// Producer sync via per-producer flag slots (no atomics).
__global__ void __launch_bounds__(NTHR) persist_kernel(const float* __restrict__ rec_w,
                                                       const float* __restrict__ fgt_w,
                                                       const float* __restrict__ dec_w,
                                                       const float* __restrict__ dec_b,
                                                       const float* __restrict__ hinit_w,
                                                       const float* __restrict__ hinit_b,
                                                       float* __restrict__ out,
                                                       int writeHidden) {
    extern __shared__ __align__(128) char smem[];
    const unsigned sbase = smem_u32(smem);
    float* Pf = (float*)smem;
    const int tid  = threadIdx.x;
    const int lane = tid & 31;
    const int ko   = tid >> 5;           // warp = k-octant
    const int bid  = blockIdx.x;
    const int jc   = bid >> 1;
    const int bh   = bid & 1;
    const bool isDec = (jc >= 64);
    const int h0   = jc * 16;
    const int oc0  = (jc - 64) * 32;

    const int matid = lane >> 3;
    const int r8    = lane & 7;

    // ---- build B mats in smem (temporary), then preload fragments ----
    for (int i = tid; i < 32 * NH; i += NTHR) {
        int col = i >> 10, k = i & 1023;
        float w;
        if (!isDec) w = (col & 1) ? fgt_w[(h0 + (col >> 1)) * NH + k]
                                  : rec_w[(h0 + (col >> 1)) * NH + k];
        else        w = dec_w[(oc0 + col) * NH + k];
        __nv_bfloat16 hi, lo;
        split_bf(w, hi, lo);
        unsigned unit = (unsigned)((k >> 4) * 8 + (col >> 3) * 2 + ((k >> 3) & 1));
        unsigned off  = unit * 128 + (k & 7) * 16 + (col & 7) * 2;
        *(__nv_bfloat16*)(smem + SM_B0 + off) = hi;
        *(__nv_bfloat16*)(smem + SM_B0 + 65536 + off) = lo;
    }
    __syncthreads();

    unsigned bHf[8][8], bLf[8][8];
#pragma unroll
    for (int kk = 0; kk < 8; kk++) {
#pragma unroll
        for (int ct = 0; ct < 2; ct++) {
            unsigned boff = (unsigned)(((ko * 8 + kk) * 8 + ct * 4 + matid) * 128 + r8 * 16);
            ldsm_x4t(&bHf[kk][ct * 4], sbase + SM_B0 + boff);
            ldsm_x4t(&bLf[kk][ct * 4], sbase + SM_B0 + 65536 + boff);
        }
    }
    __syncthreads();   // B smem dead; region reused as P

    // ---- epilogue ownership: thread -> (b, 4 h/col-pairs) ----
    const int eb  = tid >> 2;                 // local b 0..63
    const int ehl = (tid & 3) * 4;            // first of 4 owned h (local)
    const int gb  = bh * 64 + eb;             // global b
    float hold[4];
    if (!isDec) {
#pragma unroll
        for (int i = 0; i < 4; i++)
            hold[i] = __ldg(hinit_w + h0 + ehl + i) + __ldg(hinit_b + h0 + ehl + i);
    }
    float db[8];
    if (isDec) {
#pragma unroll
        for (int i = 0; i < 8; i++)
            db[i] = __ldg(dec_b + oc0 + ehl * 2 + i);
    }
    // fragment-major write coords (rec)
    const unsigned baseW = (unsigned)(jc * 8 + (gb >> 4)) * 32;
    const int lane0 = (gb & 7) * 4 + ((ehl >> 1) & 3);
    const int regi  = ((gb >> 3) & 1) + 2 * ((ehl >> 3) & 1);
    const unsigned widx = (baseW + lane0) * 4 + regi;

    for (int t = 0; t <= T_; t++) {
        const bool work = isDec || (t < T_);
        if (work) {
            const int cur = t % 3, nxtb = (t + 1) % 3;

            // ---- epilogue operand prefetch (step-independent data: hide under wait) ----
            float4 e4;
            if (!isDec)
                e4 = __ldcg((const float4*)(g_enc + (size_t)t * BNH + (size_t)gb * NH + h0 + ehl));

            // ---- wait: all 64 rec producers of this b-half finished step t-1 ----
            if (ko == 0 && t > 0) {
                const volatile unsigned* da = (const volatile unsigned*)g_doneArr[bh];
                const unsigned tgt = (unsigned)t;
                for (;;) {
                    unsigned v0 = da[lane * 8];
                    unsigned v1 = da[(lane + 32) * 8];
                    if (__all_sync(0xffffffffu, (v0 >= tgt) && (v1 >= tgt))) break;
                    __nanosleep(20);
                }
                __threadfence();
            }
            __syncthreads();

            float acc[4][4][4];
#pragma unroll
            for (int m = 0; m < 4; m++)
#pragma unroll
                for (int g = 0; g < 4; g++)
#pragma unroll
                    for (int q = 0; q < 4; q++) acc[m][g][q] = 0.f;

            const unsigned* Ah = g_hA[cur][0];
            const unsigned* Al = g_hA[cur][1];

            // ================= K loop: direct-LDG A fragments =================
#pragma unroll
            for (int kk = 0; kk < 8; kk++) {
                const int kg = ko * 8 + kk;
#pragma unroll
                for (int mt = 0; mt < 4; mt++) {
                    const int mtile = bh * 4 + mt;
                    const unsigned fidx = ((unsigned)(kg * 8 + mtile) * 32 + lane) * 4;
                    uint4 AH = __ldcg((const uint4*)(Ah + fidx));
                    uint4 AL = __ldcg((const uint4*)(Al + fidx));
                    unsigned ah[4] = {AH.x, AH.y, AH.z, AH.w};
                    unsigned al[4] = {AL.x, AL.y, AL.z, AL.w};
                    mma16816(acc[mt][0], ah, bHf[kk][0], bHf[kk][1]);
                    mma16816(acc[mt][1], ah, bHf[kk][2], bHf[kk][3]);
                    mma16816(acc[mt][2], ah, bHf[kk][4], bHf[kk][5]);
                    mma16816(acc[mt][3], ah, bHf[kk][6], bHf[kk][7]);
                    mma16816(acc[mt][0], al, bHf[kk][0], bHf[kk][1]);
                    mma16816(acc[mt][1], al, bHf[kk][2], bHf[kk][3]);
                    mma16816(acc[mt][2], al, bHf[kk][4], bHf[kk][5]);
                    mma16816(acc[mt][3], al, bHf[kk][6], bHf[kk][7]);
                    mma16816(acc[mt][0], ah, bLf[kk][0], bLf[kk][1]);
                    mma16816(acc[mt][1], ah, bLf[kk][2], bLf[kk][3]);
                    mma16816(acc[mt][2], ah, bLf[kk][4], bLf[kk][5]);
                    mma16816(acc[mt][3], ah, bLf[kk][6], bLf[kk][7]);
                }
            }

            // ---- store partials into P[ko][b][col] ----
#pragma unroll
            for (int mt = 0; mt < 4; mt++) {
#pragma unroll
                for (int g = 0; g < 4; g++) {
                    int c = g * 8 + 2 * (lane & 3);
                    int rA = mt * 16 + (lane >> 2);
                    float* p = Pf + ko * (64 * PSTR) + rA * PSTR + c;
                    *(float2*)p = make_float2(acc[mt][g][0], acc[mt][g][1]);
                    *(float2*)(p + 8 * PSTR) = make_float2(acc[mt][g][2], acc[mt][g][3]);
                }
            }
            __syncthreads();

            // ---- dec guard / signal ----
            if (tid == 0) {
                if (isDec) {
                    atomicAdd(&g_decc[bh], 1u);
                } else if (t >= 2) {
                    unsigned dt = 2u * (unsigned)(t - 1);
                    while (*(volatile unsigned*)&g_decc[bh] < dt) __nanosleep(20);
                    __threadfence();
                }
            }

            // ---- reduce 8 k-octants ----
            float R[4], F[4];
            {
                const float* pb = Pf + eb * PSTR + 2 * ehl;
                float4 q0 = *(const float4*)pb;
                float4 q1 = *(const float4*)(pb + 4);
                R[0] = q0.x; F[0] = q0.y; R[1] = q0.z; F[1] = q0.w;
                R[2] = q1.x; F[2] = q1.y; R[3] = q1.z; F[3] = q1.w;
#pragma unroll
                for (int k2 = 1; k2 < 8; k2++) {
                    const float* pk = pb + k2 * (64 * PSTR);
                    float4 s0 = *(const float4*)pk;
                    float4 s1 = *(const float4*)(pk + 4);
                    R[0] += s0.x; F[0] += s0.y; R[1] += s0.z; F[1] += s0.w;
                    R[2] += s1.x; F[2] += s1.y; R[3] += s1.z; F[3] += s1.w;
                }
            }

            // ---- fused epilogue ----
            if (!isDec) {
                const float ev[4] = {e4.x, e4.y, e4.z, e4.w};
                float hv[4], lov[4];
#pragma unroll
                for (int i = 0; i < 4; i++) {
                    float f = 1.0f / (1.0f + __expf(-F[i]));
                    float sgn = ev[i] + R[i];
                    float hn = sgn / (1.0f + fabsf(sgn));
                    float v = (1.0f - f) * hold[i] + f * hn;
                    hold[i] = v;
                    hv[i] = v;
                    __nv_bfloat16 hb16 = __float2bfloat16(v);
                    lov[i] = v - __bfloat162float(hb16);
                }
                unsigned* wH = g_hA[nxtb][0];
                unsigned* wL = g_hA[nxtb][1];
                wH[widx]     = pack2(hv[0], hv[1]);
                wH[widx + 4] = pack2(hv[2], hv[3]);
                wL[widx]     = pack2(lov[0], lov[1]);
                wL[widx + 4] = pack2(lov[2], lov[3]);
                __threadfence();
                __syncthreads();
                if (tid == 0)
                    *((volatile unsigned*)&g_doneArr[bh][jc * 8]) = (unsigned)(t + 1);
            } else if (t >= 1) {
                float* op = out + (size_t)(t - 1) * (B_ * NO) + (size_t)gb * NO + oc0 + ehl * 2;
                float4 v0 = make_float4(R[0] + db[0], F[0] + db[1], R[1] + db[2], F[1] + db[3]);
                float4 v1 = make_float4(R[2] + db[4], F[2] + db[5], R[3] + db[6], F[3] + db[7]);
                *(float4*)op = v0;
                *(float4*)(op + 4) = v1;
                __syncthreads();   // done reading P before next step's STS
            } else {
                __syncthreads();
            }
        }
        if (t == T_) break;
    }

    // ---- final hidden -> out tail [b][h] (from registers) ----
    if (writeHidden && !isDec) {
        float* dst = out + (size_t)T_ * B_ * NO + (size_t)gb * NH + h0 + ehl;
        *(float4*)dst = make_float4(hold[0], hold[1], hold[2], hold[3]);
    }
}

// --------------------------------------------------------------------------------
extern "C" void kernel_launch(void* const* d_in, const int* in_sizes, int n_in,
                              void* d_out, int out_size) {
    const float* x       = (const float*)d_in[0];
    const float* enc_w   = (const float*)d_in[1];
    const float* enc_b   = (const float*)d_in[2];
    const float* rec_w   = (const float*)d_in[3];
    const float* fgt_w   = (const float*)d_in[4];
    const float* dec_w   = (const float*)d_in[5];
    const float* dec_b   = (const float*)d_in[6];
    const float* hinit_w = (const float*)d_in[7];
    const float* hinit_b = (const float*)d_in[8];
    float* out = (float*)d_out;

    reset_kernel<<<1, 256>>>();
    init_hidden_kernel<<<(B_ * NH + 255) / 256, 256>>>(hinit_w, hinit_b);

    dim3 eg(T_ * B_ / 32, NH / 64);
    enc_kernel<<<eg, 256>>>(x, enc_w, enc_b);

    cudaFuncSetAttribute(persist_kernel, cudaFuncAttributeMaxDynamicSharedMemorySize,
                         SMEM_BYTES);
    int writeHidden = (out_size >= T_ * B_ * NO + B_ * NH) ? 1 : 0;
    persist_kernel<<<NCTA, NTHR, SMEM_BYTES>>>(rec_w, fgt_w, dec_w, dec_b,
                                               hinit_w, hinit_b, out, writeHidden);
}